// round 14
// baseline (speedup 1.0000x reference)
#include <cuda_runtime.h>
#include <cuda_fp16.h>
#include <math.h>

// Problem constants
#define Bb      8
#define Nn      2048
#define Cc      256
#define Ee      32768
#define Hh      8
#define CO      64
#define BN_TOT  (Bb * Nn)          // 16384 nodes
#define F       (Hh * CO)          // 512 features
#define BE      (Bb * Ee)          // 262144 real edges
#define ET      (BE + BN_TOT)      // 278528 edges incl. self loops
#define NEG     0.2f
#define CAP     96                 // per-dst bucket capacity

// ---------------- scratch (static device globals; no allocation) ----------------
__device__ __half   g_xt[(size_t)BN_TOT * F];   // projected features, fp16, 16 MB
__device__ __half   g_xh[(size_t)BN_TOT * Cc];  // input x in fp16, 8 MB
__device__ unsigned g_wp[(Cc / 2) * F];         // W packed half2{k even, k odd}, 256 KB
__device__ float    g_asrc[BN_TOT * Hh];
__device__ float    g_adst[BN_TOT * Hh];
__device__ int      g_cnt[BN_TOT];
__device__ int      g_bucket[(size_t)BN_TOT * CAP];

// ---------------- cp.async helpers ----------------------------------------------
__device__ __forceinline__ void cp16(void* smem, const void* g) {
    unsigned saddr = (unsigned)__cvta_generic_to_shared(smem);
    asm volatile("cp.async.cg.shared.global [%0], [%1], 16;" :: "r"(saddr), "l"(g));
}
#define CP_COMMIT()  asm volatile("cp.async.commit_group;")
#define CP_WAIT(n)   asm volatile("cp.async.wait_group %0;" :: "n"(n))

// ---------------- prep: x -> fp16 ------------------------------------------------
__global__ void prep_x_kernel(const float* __restrict__ x) {
    int i = blockIdx.x * blockDim.x + threadIdx.x;      // handles 4 floats
    float4 v = ((const float4*)x)[i];
    __half2 h0 = __floats2half2_rn(v.x, v.y);
    __half2 h1 = __floats2half2_rn(v.z, v.w);
    ((uint2*)g_xh)[i] = make_uint2(*(unsigned*)&h0, *(unsigned*)&h1);
}

// ---------------- prep: W -> k-pair packed half2 ---------------------------------
// g_wp[k2 * F + n] = half2{ W[2k2][n], W[2k2+1][n] }
__global__ void prep_w_kernel(const float* __restrict__ W) {
    int i = blockIdx.x * blockDim.x + threadIdx.x;      // 0 .. 128*512-1
    int k2 = i >> 9;
    int n  = i & (F - 1);
    float a = W[(size_t)(2 * k2) * F + n];
    float b = W[(size_t)(2 * k2 + 1) * F + n];
    __half2 h = __floats2half2_rn(a, b);
    g_wp[i] = *(unsigned*)&h;
}

// ---------------- decode edges (+ self loops) straight into dst buckets ---------
__global__ void decode_place_kernel(const void* __restrict__ eiv) {
    const unsigned* w = (const unsigned*)eiv;
    unsigned hv = w[2 * (threadIdx.x & 31) + 1];
    int is64 = __all_sync(0xffffffffu, hv == 0u);

    int e0 = (blockIdx.x * blockDim.x + threadIdx.x) * 4;
    if (e0 >= ET) return;

    int s[4], d[4];
    if (e0 < BE) {
        int k = e0 & (Ee - 1);
        int off = (e0 >> 15) * Nn;
        if (is64) {
            const long long* p = (const long long*)eiv;
            longlong2 s01 = *(const longlong2*)(p + k);
            longlong2 s23 = *(const longlong2*)(p + k + 2);
            longlong2 d01 = *(const longlong2*)(p + Ee + k);
            longlong2 d23 = *(const longlong2*)(p + Ee + k + 2);
            s[0] = (int)s01.x; s[1] = (int)s01.y; s[2] = (int)s23.x; s[3] = (int)s23.y;
            d[0] = (int)d01.x; d[1] = (int)d01.y; d[2] = (int)d23.x; d[3] = (int)d23.y;
        } else {
            const int* p = (const int*)eiv;
            int4 sv = *(const int4*)(p + k);
            int4 dv = *(const int4*)(p + Ee + k);
            s[0] = sv.x; s[1] = sv.y; s[2] = sv.z; s[3] = sv.w;
            d[0] = dv.x; d[1] = dv.y; d[2] = dv.z; d[3] = dv.w;
        }
#pragma unroll
        for (int i = 0; i < 4; i++) { s[i] += off; d[i] += off; }
    } else {
#pragma unroll
        for (int i = 0; i < 4; i++) { s[i] = d[i] = e0 - BE + i; }
    }

#pragma unroll
    for (int i = 0; i < 4; i++) {
        int slot = atomicAdd(&g_cnt[d[i]], 1);
        if (slot < CAP) g_bucket[(size_t)d[i] * CAP + slot] = s[i];
    }
}

// ---------------- fp16 tensor-core GEMM, cp.async double-buffered ---------------
#define MMA_F16(d, a, b)                                                          \
    asm volatile("mma.sync.aligned.m16n8k16.row.col.f32.f16.f16.f32 "             \
                 "{%0,%1,%2,%3}, {%4,%5,%6,%7}, {%8,%9}, {%0,%1,%2,%3};"          \
                 : "+f"(d[0]), "+f"(d[1]), "+f"(d[2]), "+f"(d[3])                  \
                 : "r"(a[0]), "r"(a[1]), "r"(a[2]), "r"(a[3]), "r"(b[0]), "r"(b[1]))

__global__ void __launch_bounds__(256, 2)
gemm_kernel(const float* __restrict__ att_src, const float* __restrict__ att_dst) {
    __shared__ __half   As[2][128][40];      // [m][k] fp16, 2 x 10 KB
    __shared__ unsigned Bp[2][16][136];      // [k2][n] half2 words, 2 x 8.5 KB

    const int tid  = threadIdx.x;
    const int lane = tid & 31;
    const int wid  = tid >> 5;
    const int wr   = wid >> 1;
    const int wc   = wid & 1;
    const int bx   = blockIdx.x;             // 0..3
    const int by   = blockIdx.y;             // 0..127
    const int qr   = lane >> 2;
    const int qc   = lane & 3;

    // loader indices (per stage: 2 x 16B for A, 2 x 16B for B per thread)
    const int ar  = tid >> 1;                // 0..127 (A row, 2 chunks per row)
    const int acg = (tid & 1) * 16;          // 0 or 16 (halves)
    const int bkr = tid >> 5;                // 0..7 (B k2 row base, +8 for 2nd)
    const int bc4 = (lane) * 4;              // 0..124 (uints)

    const __half*   Asrc = g_xh + (size_t)(by * 128 + ar) * Cc + acg;
    const unsigned* Bsrc = g_wp + (size_t)bkr * F + bx * 128 + bc4;

    float acc[2][8][4];
#pragma unroll
    for (int i = 0; i < 2; i++)
#pragma unroll
        for (int j = 0; j < 8; j++)
#pragma unroll
            for (int k = 0; k < 4; k++) acc[i][j][k] = 0.0f;

    // prologue: stage 0
    {
        cp16(&As[0][ar][acg],      Asrc);
        cp16(&As[0][ar][acg + 8],  Asrc + 8);
        cp16(&Bp[0][bkr][bc4],     Bsrc);
        cp16(&Bp[0][bkr + 8][bc4], Bsrc + (size_t)8 * F);
    }
    CP_COMMIT();

    for (int kk = 0; kk < 8; kk++) {         // 8 stages of BK=32
        int buf = kk & 1;
        if (kk < 7) {
            int nb = (kk + 1) & 1;
            const __half*   a2 = Asrc + (kk + 1) * 32;
            const unsigned* b2 = Bsrc + (size_t)(kk + 1) * 16 * F;
            cp16(&As[nb][ar][acg],      a2);
            cp16(&As[nb][ar][acg + 8],  a2 + 8);
            cp16(&Bp[nb][bkr][bc4],     b2);
            cp16(&Bp[nb][bkr + 8][bc4], b2 + (size_t)8 * F);
            CP_COMMIT();
            CP_WAIT(1);
        } else {
            CP_WAIT(0);
        }
        __syncthreads();

#pragma unroll
        for (int ks = 0; ks < 2; ks++) {
            unsigned a[2][4];
            const int kkk = ks * 16 + 2 * qc;
#pragma unroll
            for (int mt = 0; mt < 2; mt++) {
                int rm = wr * 32 + mt * 16 + qr;
                a[mt][0] = *(const unsigned*)&As[buf][rm][kkk];
                a[mt][1] = *(const unsigned*)&As[buf][rm + 8][kkk];
                a[mt][2] = *(const unsigned*)&As[buf][rm][kkk + 8];
                a[mt][3] = *(const unsigned*)&As[buf][rm + 8][kkk + 8];
            }
            unsigned b[8][2];
            const int kb = ks * 8 + qc;
#pragma unroll
            for (int nt = 0; nt < 8; nt++) {
                int col = wc * 64 + nt * 8 + qr;
                b[nt][0] = Bp[buf][kb][col];
                b[nt][1] = Bp[buf][kb + 4][col];
            }
#pragma unroll
            for (int mt = 0; mt < 2; mt++)
#pragma unroll
                for (int nt = 0; nt < 8; nt++)
                    MMA_F16(acc[mt][nt], a[mt], b[nt]);
        }
        __syncthreads();
    }

    // epilogue: fp16 xt store
#pragma unroll
    for (int mt = 0; mt < 2; mt++) {
        int r = by * 128 + wr * 32 + mt * 16 + qr;
#pragma unroll
        for (int nt = 0; nt < 8; nt++) {
            int c = bx * 128 + wc * 64 + nt * 8 + 2 * qc;
            *(__half2*)(g_xt + (size_t)r * F + c) =
                __floats2half2_rn(acc[mt][nt][0], acc[mt][nt][1]);
            *(__half2*)(g_xt + (size_t)(r + 8) * F + c) =
                __floats2half2_rn(acc[mt][nt][2], acc[mt][nt][3]);
        }
    }

    // fused attdot (fp32 accumulators): head h = bx*2 + wc
    {
        const int h = bx * 2 + wc;
        const float* asv = att_src + h * CO;
        const float* adv = att_dst + h * CO;
        float s_att[16], d_att[16];
#pragma unroll
        for (int nt = 0; nt < 8; nt++) {
            int c = nt * 8 + 2 * qc;
            s_att[2 * nt]     = asv[c];
            s_att[2 * nt + 1] = asv[c + 1];
            d_att[2 * nt]     = adv[c];
            d_att[2 * nt + 1] = adv[c + 1];
        }
#pragma unroll
        for (int mt = 0; mt < 2; mt++) {
            float s0 = 0.f, d0 = 0.f, s1 = 0.f, d1 = 0.f;
#pragma unroll
            for (int nt = 0; nt < 8; nt++) {
                s0 += acc[mt][nt][0] * s_att[2 * nt] + acc[mt][nt][1] * s_att[2 * nt + 1];
                d0 += acc[mt][nt][0] * d_att[2 * nt] + acc[mt][nt][1] * d_att[2 * nt + 1];
                s1 += acc[mt][nt][2] * s_att[2 * nt] + acc[mt][nt][3] * s_att[2 * nt + 1];
                d1 += acc[mt][nt][2] * d_att[2 * nt] + acc[mt][nt][3] * d_att[2 * nt + 1];
            }
#pragma unroll
            for (int o = 1; o <= 2; o <<= 1) {
                s0 += __shfl_xor_sync(0xffffffffu, s0, o);
                d0 += __shfl_xor_sync(0xffffffffu, d0, o);
                s1 += __shfl_xor_sync(0xffffffffu, s1, o);
                d1 += __shfl_xor_sync(0xffffffffu, d1, o);
            }
            if (qc == 0) {
                int n0 = by * 128 + wr * 32 + mt * 16 + qr;
                g_asrc[n0 * Hh + h] = s0;
                g_adst[n0 * Hh + h] = d0;
                g_asrc[(n0 + 8) * Hh + h] = s1;
                g_adst[(n0 + 8) * Hh + h] = d1;
            }
        }
    }
}

// ---------------- fused softmax + weighted gather, ALL 8 heads per block --------
__global__ void gather_kernel(float* __restrict__ out, const float* __restrict__ bias) {
    int n = blockIdx.x;
    int h = threadIdx.x >> 5;
    int lane = threadIdx.x & 31;
    int q = lane >> 3;
    int cl = lane & 7;
    int deg = g_cnt[n];
    if (deg > CAP) deg = CAP;
    const int* bucket = g_bucket + (size_t)n * CAP;

    float adstv = g_adst[n * Hh + h];
    const __half* xb = g_xt + h * CO + cl * 8;

    float acc[8] = {0.f, 0.f, 0.f, 0.f, 0.f, 0.f, 0.f, 0.f};

    if (deg <= 32) {
        int s = 0;
        float l = -1e30f;
        if (lane < deg) {
            s = bucket[lane];
            float t = g_asrc[s * Hh + h] + adstv;
            l = (t > 0.0f) ? t : NEG * t;
        }
        float m = l;
#pragma unroll
        for (int o = 16; o; o >>= 1) m = fmaxf(m, __shfl_xor_sync(0xffffffffu, m, o));
        float wgt = (lane < deg) ? __expf(l - m) : 0.0f;
        float sum = wgt;
#pragma unroll
        for (int o = 16; o; o >>= 1) sum += __shfl_xor_sync(0xffffffffu, sum, o);
        float a = wgt / (sum + 1e-16f);

        int dr = (deg + 7) & ~7;
        for (int j = 0; j < dr; j += 8) {
            float a0 = __shfl_sync(0xffffffffu, a, j + q);
            int   s0 = __shfl_sync(0xffffffffu, s, j + q);
            float a1 = __shfl_sync(0xffffffffu, a, j + 4 + q);
            int   s1 = __shfl_sync(0xffffffffu, s, j + 4 + q);
            uint4 u0 = *(const uint4*)(xb + (size_t)s0 * F);
            uint4 u1 = *(const uint4*)(xb + (size_t)s1 * F);
            float2 f0 = __half22float2(*(__half2*)&u0.x);
            float2 f1 = __half22float2(*(__half2*)&u0.y);
            float2 f2 = __half22float2(*(__half2*)&u0.z);
            float2 f3 = __half22float2(*(__half2*)&u0.w);
            acc[0] += a0 * f0.x; acc[1] += a0 * f0.y;
            acc[2] += a0 * f1.x; acc[3] += a0 * f1.y;
            acc[4] += a0 * f2.x; acc[5] += a0 * f2.y;
            acc[6] += a0 * f3.x; acc[7] += a0 * f3.y;
            f0 = __half22float2(*(__half2*)&u1.x);
            f1 = __half22float2(*(__half2*)&u1.y);
            f2 = __half22float2(*(__half2*)&u1.z);
            f3 = __half22float2(*(__half2*)&u1.w);
            acc[0] += a1 * f0.x; acc[1] += a1 * f0.y;
            acc[2] += a1 * f1.x; acc[3] += a1 * f1.y;
            acc[4] += a1 * f2.x; acc[5] += a1 * f2.y;
            acc[6] += a1 * f3.x; acc[7] += a1 * f3.y;
        }
    } else {
        float m = -1e30f;
        for (int i = lane; i < deg; i += 32) {
            int s = bucket[i];
            float t = g_asrc[s * Hh + h] + adstv;
            t = (t > 0.0f) ? t : NEG * t;
            m = fmaxf(m, t);
        }
#pragma unroll
        for (int o = 16; o; o >>= 1) m = fmaxf(m, __shfl_xor_sync(0xffffffffu, m, o));

        float sum = 0.0f;
        for (int i = lane; i < deg; i += 32) {
            int s = bucket[i];
            float t = g_asrc[s * Hh + h] + adstv;
            t = (t > 0.0f) ? t : NEG * t;
            sum += __expf(t - m);
        }
#pragma unroll
        for (int o = 16; o; o >>= 1) sum += __shfl_xor_sync(0xffffffffu, sum, o);
        float inv = 1.0f / (sum + 1e-16f);

        for (int base = 0; base < deg; base += 32) {
            int i = base + lane;
            int sreg = 0;
            float areg = 0.0f;
            if (i < deg) {
                sreg = bucket[i];
                float t = g_asrc[sreg * Hh + h] + adstv;
                t = (t > 0.0f) ? t : NEG * t;
                areg = __expf(t - m) * inv;
            }
            int cnt = deg - base;
            if (cnt > 32) cnt = 32;
            int cr = (cnt + 7) & ~7;
            for (int j = 0; j < cr; j += 8) {
                float a0 = __shfl_sync(0xffffffffu, areg, j + q);
                int   s0 = __shfl_sync(0xffffffffu, sreg, j + q);
                float a1 = __shfl_sync(0xffffffffu, areg, j + 4 + q);
                int   s1 = __shfl_sync(0xffffffffu, sreg, j + 4 + q);
                uint4 u0 = *(const uint4*)(xb + (size_t)s0 * F);
                uint4 u1 = *(const uint4*)(xb + (size_t)s1 * F);
                float2 f0 = __half22float2(*(__half2*)&u0.x);
                float2 f1 = __half22float2(*(__half2*)&u0.y);
                float2 f2 = __half22float2(*(__half2*)&u0.z);
                float2 f3 = __half22float2(*(__half2*)&u0.w);
                acc[0] += a0 * f0.x; acc[1] += a0 * f0.y;
                acc[2] += a0 * f1.x; acc[3] += a0 * f1.y;
                acc[4] += a0 * f2.x; acc[5] += a0 * f2.y;
                acc[6] += a0 * f3.x; acc[7] += a0 * f3.y;
                f0 = __half22float2(*(__half2*)&u1.x);
                f1 = __half22float2(*(__half2*)&u1.y);
                f2 = __half22float2(*(__half2*)&u1.z);
                f3 = __half22float2(*(__half2*)&u1.w);
                acc[0] += a1 * f0.x; acc[1] += a1 * f0.y;
                acc[2] += a1 * f1.x; acc[3] += a1 * f1.y;
                acc[4] += a1 * f2.x; acc[5] += a1 * f2.y;
                acc[6] += a1 * f3.x; acc[7] += a1 * f3.y;
            }
        }
    }

#pragma unroll
    for (int i = 0; i < 8; i++) {
        acc[i] += __shfl_xor_sync(0xffffffffu, acc[i], 8);
        acc[i] += __shfl_xor_sync(0xffffffffu, acc[i], 16);
    }

    if (q == 0) {
        int c = h * CO + cl * 8;
        float4 b0 = *(const float4*)(bias + c);
        float4 b1 = *(const float4*)(bias + c + 4);
        float* o = out + (size_t)n * F + c;
        *(float4*)(o)     = make_float4(acc[0] + b0.x, acc[1] + b0.y,
                                        acc[2] + b0.z, acc[3] + b0.w);
        *(float4*)(o + 4) = make_float4(acc[4] + b1.x, acc[5] + b1.y,
                                        acc[6] + b1.z, acc[7] + b1.w);
    }
}

// ---------------- launch ----------------------------------------------------------
extern "C" void kernel_launch(void* const* d_in, const int* in_sizes, int n_in,
                              void* d_out, int out_size) {
    const float* x    = (const float*)d_in[0];
    const void*  ei   = d_in[1];
    const float* W    = (const float*)d_in[2];
    const float* asrc = (const float*)d_in[3];
    const float* adst = (const float*)d_in[4];
    const float* bias = (const float*)d_in[5];
    float* out = (float*)d_out;

    static cudaStream_t s2 = nullptr;
    static cudaEvent_t ev_fork = nullptr, ev_gemm = nullptr;
    static void* cnt_ptr = nullptr;
    if (s2 == nullptr) {
        cudaStreamCreateWithFlags(&s2, cudaStreamNonBlocking);
        cudaEventCreateWithFlags(&ev_fork, cudaEventDisableTiming);
        cudaEventCreateWithFlags(&ev_gemm, cudaEventDisableTiming);
        cudaGetSymbolAddress(&cnt_ptr, g_cnt);
    }

    cudaEventRecord(ev_fork, 0);
    cudaStreamWaitEvent(s2, ev_fork, 0);

    // s2: prep inputs to fp16, then double-buffered tensor GEMM + fused attdot
    prep_x_kernel<<<(BN_TOT * Cc / 4) / 256, 256, 0, s2>>>(x);
    prep_w_kernel<<<(Cc / 2) * F / 256, 256, 0, s2>>>(W);
    gemm_kernel<<<dim3(4, BN_TOT / 128), 256, 0, s2>>>(asrc, adst);
    cudaEventRecord(ev_gemm, s2);

    // main: bucket build (one pass)
    cudaMemsetAsync(cnt_ptr, 0, BN_TOT * sizeof(int), 0);
    decode_place_kernel<<<(ET / 4 + 255) / 256, 256>>>(ei);

    // join: merged gather over all 8 heads
    cudaStreamWaitEvent(0, ev_gemm, 0);
    gather_kernel<<<BN_TOT, 256>>>(out, bias);
}